// round 13
// baseline (speedup 1.0000x reference)
#include <cuda_runtime.h>
#include <cuda_fp16.h>
#include <cstdint>
#include <math.h>

#define BATCH 8192
#define IN_F  1024
#define OUT_F 1024
#define NB    8
#define KDIM  (IN_F * 9)          // 9216

// Scratch (__device__ globals — sanctioned)
__device__ __half g_Ah[(size_t)BATCH * KDIM];   // [b][c*1024+i]
__device__ __half g_Wh[(size_t)OUT_F * KDIM];   // [o][c*1024+i]  (B as [N,K])

// ---------------------------------------------------------------------------
// prep_w: augmented weights, transposed to [OUT_F, KDIM], fp16. (14us measured)
// ---------------------------------------------------------------------------
__global__ void prep_w(const float* __restrict__ bw,
                       const float* __restrict__ sw,
                       const float* __restrict__ sc) {
    __shared__ float tile[9][32][33];
    const int i0 = (blockIdx.x & 31) * 32;
    const int o0 = (blockIdx.x >> 5) * 32;
    const int tid = threadIdx.x;                 // 256

    { // c = 0 : base_weight[o, i] — coalesced over i
        int ti = tid & 31, to = tid >> 5;
#pragma unroll
        for (int p = 0; p < 4; ++p) {
            int ol = to + p * 8;
            tile[0][ol][ti] = bw[(size_t)(o0 + ol) * IN_F + i0 + ti];
        }
    }
    { // splines — coalesced over o
        int to = tid & 31, ti = tid >> 5;
#pragma unroll
        for (int p = 0; p < 4; ++p) {
            int il = ti + p * 8;
            int i = i0 + il;
            float scale = sc[(size_t)i * OUT_F + o0 + to];
#pragma unroll
            for (int k = 0; k < NB; ++k)
                tile[1 + k][to][il] = sw[((size_t)i * NB + k) * OUT_F + o0 + to] * scale;
        }
    }
    __syncthreads();
    { // write g_Wh[o][c*1024+i] — coalesced over i
        int il = tid & 31, ol0 = tid >> 5;
#pragma unroll
        for (int p = 0; p < 4; ++p) {
            int ol = ol0 + p * 8;
            size_t orow = (size_t)(o0 + ol) * KDIM;
#pragma unroll
            for (int c = 0; c < 9; ++c)
                g_Wh[orow + (size_t)c * IN_F + i0 + il] =
                    __float2half_rn(tile[c][ol][il]);
        }
    }
}

// ---------------------------------------------------------------------------
// prep_act — EXACT R9 v3 (measured best ~90us): uniform-knot closed form,
// 2 elements/thread, fully coalesced half2 stores, zeros explicit.
// ---------------------------------------------------------------------------
__device__ __forceinline__ float pick_w(int j, int m, float w0, float w1,
                                        float w2, float w3) {
    int tt = j - m + 3;
    return tt == 0 ? w0 : tt == 1 ? w1 : tt == 2 ? w2 : tt == 3 ? w3 : 0.0f;
}

__global__ void prep_act(const float* __restrict__ x,
                         const float* __restrict__ grid) {
    const float t0 = __ldg(&grid[0]);
    const float invh = 11.0f / (__ldg(&grid[11]) - t0);

    int idx = (blockIdx.x * 256 + threadIdx.x) * 2;      // 2 adjacent elements
    int b = idx >> 10, i = idx & 1023;
    float2 xv2 = *(const float2*)(x + idx);
    __half* arow = g_Ah + (size_t)b * KDIM + i;

    float w0[2], w1[2], w2[2], w3[2], sl[2];
    int m[2];
#pragma unroll
    for (int e = 0; e < 2; ++e) {
        float xv = e ? xv2.y : xv2.x;
        sl[e] = __fdividef(xv, 1.0f + __expf(-xv));
        float u = (xv - t0) * invh;
        float mf = floorf(u);
        m[e] = (int)mf;
        float f = u - mf;
        float f2 = f * f, f3 = f2 * f;
        w3[e] = f3 * (1.0f / 6.0f);
        w0[e] = (1.0f / 6.0f) - 0.5f * f + 0.5f * f2 - w3[e];
        w1[e] = 0.5f * f3 - f2 + (2.0f / 3.0f);
        w2[e] = -0.5f * f3 + 0.5f * f2 + 0.5f * f + (1.0f / 6.0f);
    }

    *(__half2*)arow = __floats2half2_rn(sl[0], sl[1]);
#pragma unroll
    for (int j = 0; j < 8; ++j) {
        float v0 = pick_w(j, m[0], w0[0], w1[0], w2[0], w3[0]);
        float v1 = pick_w(j, m[1], w0[1], w1[1], w2[1], w3[1]);
        *(__half2*)(arow + (size_t)(1 + j) * IN_F) = __floats2half2_rn(v0, v1);
    }
}

// ---------------------------------------------------------------------------
// fp16 GEMM — R12 structure (BK=128, 72 iters, STAGES=2) with ONE isolated
// change: B fragments via paired ldmatrix x4 (2 instr) instead of 4x ldsm x2.
// x4 reg map: r0=(ntEven,k0) r1=(ntOdd,k0) r2=(ntEven,k1) r3=(ntOdd,k1).
// CTA 128x256, 512 thr (16 warps, warp 64x32), SW128 smem, m16n8k16 f32 accum.
// ---------------------------------------------------------------------------
#define BM 128
#define BN 256
#define BK 128
#define KITERS (KDIM / BK)        // 72
#define STAGES 2
#define A_SUB (BM * 128)          // 16384 bytes per 64-k A sub-tile
#define B_SUB (BN * 128)          // 32768 bytes per 64-k B sub-tile
#define A_BYTES (2 * A_SUB)       // 32768
#define B_BYTES (2 * B_SUB)       // 65536
#define STG_BYTES (A_BYTES + B_BYTES)          // 98304
#define GEMM_SMEM (STAGES * STG_BYTES)         // 196608

__device__ __forceinline__ uint32_t smem_u32(const void* p) {
    uint32_t a;
    asm("{ .reg .u64 t; cvta.to.shared.u64 t, %1; cvt.u32.u64 %0, t; }" : "=r"(a) : "l"(p));
    return a;
}
__device__ __forceinline__ void cp16(uint32_t dst, const void* src) {
    asm volatile("cp.async.cg.shared.global [%0], [%1], 16;\n" :: "r"(dst), "l"(src));
}
__device__ __forceinline__ void ldsm_x4(uint32_t* r, uint32_t addr) {
    asm volatile("ldmatrix.sync.aligned.m8n8.x4.shared.b16 {%0,%1,%2,%3}, [%4];"
                 : "=r"(r[0]), "=r"(r[1]), "=r"(r[2]), "=r"(r[3]) : "r"(addr));
}
__device__ __forceinline__ void mma_f16(float* c, const uint32_t* a,
                                        uint32_t b0, uint32_t b1) {
    asm volatile(
        "mma.sync.aligned.m16n8k16.row.col.f32.f16.f16.f32 "
        "{%0,%1,%2,%3}, {%4,%5,%6,%7}, {%8,%9}, {%0,%1,%2,%3};\n"
        : "+f"(c[0]), "+f"(c[1]), "+f"(c[2]), "+f"(c[3])
        : "r"(a[0]), "r"(a[1]), "r"(a[2]), "r"(a[3]), "r"(b0), "r"(b1));
}

// Loads one 128-k stage = two 64-k sub-tiles for A and B.
__device__ __forceinline__ void load_stage(uint32_t sbase, int slot,
                                           int m0, int n0, int k0, int tid) {
    uint32_t sd = sbase + slot * STG_BYTES;
#pragma unroll
    for (int h = 0; h < 2; ++h) {              // A sub-tiles
        uint32_t sda = sd + h * A_SUB;
        int kh = k0 + h * 64;
#pragma unroll
        for (int t = 0; t < 2; ++t) {          // 1024 chunks of 16B
            int idx = tid + t * 512;
            int row = idx >> 3, c = idx & 7;
            cp16(sda + row * 128 + ((c ^ (row & 7)) << 4),
                 g_Ah + (size_t)(m0 + row) * KDIM + kh + c * 8);
        }
    }
    uint32_t sdb = sd + A_BYTES;
#pragma unroll
    for (int h = 0; h < 2; ++h) {              // B sub-tiles
        uint32_t sdbh = sdb + h * B_SUB;
        int kh = k0 + h * 64;
#pragma unroll
        for (int t = 0; t < 4; ++t) {          // 2048 chunks of 16B
            int idx = tid + t * 512;
            int row = idx >> 3, c = idx & 7;
            cp16(sdbh + row * 128 + ((c ^ (row & 7)) << 4),
                 g_Wh + (size_t)(n0 + row) * KDIM + kh + c * 8);
        }
    }
}

__global__ void __launch_bounds__(512, 1)
kan_gemm(float* __restrict__ C) {
    extern __shared__ char smem[];
    const uint32_t sbase = smem_u32(smem);

    const int tid = threadIdx.x;
    const int warp = tid >> 5, lane = tid & 31;
    const int wm = warp & 1;          // 2 m-warps   -> 64 rows each
    const int wn = warp >> 1;         // 8 n-warps   -> 32 cols each
    const int g = lane >> 2, tg = lane & 3;
    const int m0 = blockIdx.y * BM;
    const int n0 = blockIdx.x * BN;

    // Per-lane ldmatrix address components (x4 for both A and B)
    const int kt = lane >> 4;                  // half-warp k-chunk select
    int a_row[4], b_row[2];
#pragma unroll
    for (int mt = 0; mt < 4; ++mt) a_row[mt] = wm * 64 + mt * 16 + (lane & 15);
#pragma unroll
    for (int p = 0; p < 2; ++p)   b_row[p] = wn * 32 + p * 16 + (lane & 15);

    float acc[4][4][4];
#pragma unroll
    for (int a = 0; a < 4; ++a)
#pragma unroll
        for (int b = 0; b < 4; ++b)
#pragma unroll
            for (int c = 0; c < 4; ++c) acc[a][b][c] = 0.0f;

    // Prologue: stage 0
    load_stage(sbase, 0, m0, n0, 0, tid);
    asm volatile("cp.async.commit_group;\n" ::);

    for (int it = 0; it < KITERS; ++it) {
        asm volatile("cp.async.wait_group 0;\n" ::);
        __syncthreads();

        if (it + 1 < KITERS)
            load_stage(sbase, (it + 1) & 1, m0, n0, (it + 1) * BK, tid);
        asm volatile("cp.async.commit_group;\n" ::);

        const uint32_t sa = sbase + (it & 1) * STG_BYTES;
        const uint32_t sb = sa + A_BYTES;

#pragma unroll
        for (int kk = 0; kk < BK / 16; ++kk) {      // 8 k-chunks; sub-tile = kk>>2
            const uint32_t sah = sa + (kk >> 2) * A_SUB;
            const uint32_t sbh = sb + (kk >> 2) * B_SUB;
            const int kk2 = kk & 3;
            uint32_t af[4][4], bp[2][4];
#pragma unroll
            for (int mt = 0; mt < 4; ++mt) {
                int r = a_row[mt];
                ldsm_x4(af[mt], sah + r * 128 + (((kk2 * 2 + kt) ^ (r & 7)) << 4));
            }
#pragma unroll
            for (int p = 0; p < 2; ++p) {
                int r = b_row[p];
                ldsm_x4(bp[p], sbh + r * 128 + (((kk2 * 2 + kt) ^ (r & 7)) << 4));
            }
#pragma unroll
            for (int mt = 0; mt < 4; ++mt)
#pragma unroll
                for (int nt = 0; nt < 4; ++nt)
                    mma_f16(acc[mt][nt], af[mt],
                            bp[nt >> 1][nt & 1], bp[nt >> 1][(nt & 1) + 2]);
        }
    }

    // Epilogue
#pragma unroll
    for (int mt = 0; mt < 4; ++mt) {
        int r0 = m0 + wm * 64 + mt * 16 + g;
#pragma unroll
        for (int nt = 0; nt < 4; ++nt) {
            int col = n0 + wn * 32 + nt * 8 + 2 * tg;
            *(float2*)(C + (size_t)r0 * OUT_F + col) =
                make_float2(acc[mt][nt][0], acc[mt][nt][1]);
            *(float2*)(C + (size_t)(r0 + 8) * OUT_F + col) =
                make_float2(acc[mt][nt][2], acc[mt][nt][3]);
        }
    }
}

// ---------------------------------------------------------------------------
extern "C" void kernel_launch(void* const* d_in, const int* in_sizes, int n_in,
                              void* d_out, int out_size) {
    const float* x    = (const float*)d_in[0];
    const float* grid = (const float*)d_in[1];
    const float* bw   = (const float*)d_in[2];
    const float* sw   = (const float*)d_in[3];
    const float* sc   = (const float*)d_in[4];
    float* out = (float*)d_out;

    prep_w<<<1024, 256>>>(bw, sw, sc);
    prep_act<<<(BATCH * IN_F) / 512, 256>>>(x, grid);

    cudaFuncSetAttribute(kan_gemm, cudaFuncAttributeMaxDynamicSharedMemorySize, GEMM_SMEM);
    dim3 grd(OUT_F / BN, BATCH / BM);   // 4 x 64 = 256 CTAs
    kan_gemm<<<grd, 512, GEMM_SMEM>>>(out);
}

// round 14
// speedup vs baseline: 1.1417x; 1.1417x over previous
#include <cuda_runtime.h>
#include <cuda_fp16.h>
#include <cstdint>
#include <math.h>

#define BATCH 8192
#define IN_F  1024
#define OUT_F 1024
#define NB    8
#define KDIM  (IN_F * 9)          // 9216

// Scratch (__device__ globals — sanctioned)
__device__ __half g_Ah[(size_t)BATCH * KDIM];   // [b][c*1024+i]
__device__ __half g_Wh[(size_t)OUT_F * KDIM];   // [o][c*1024+i]  (B as [N,K])

// ---------------------------------------------------------------------------
// prep_w: augmented weights, transposed to [OUT_F, KDIM], fp16. (14us measured)
// ---------------------------------------------------------------------------
__global__ void prep_w(const float* __restrict__ bw,
                       const float* __restrict__ sw,
                       const float* __restrict__ sc) {
    __shared__ float tile[9][32][33];
    const int i0 = (blockIdx.x & 31) * 32;
    const int o0 = (blockIdx.x >> 5) * 32;
    const int tid = threadIdx.x;                 // 256

    { // c = 0 : base_weight[o, i] — coalesced over i
        int ti = tid & 31, to = tid >> 5;
#pragma unroll
        for (int p = 0; p < 4; ++p) {
            int ol = to + p * 8;
            tile[0][ol][ti] = bw[(size_t)(o0 + ol) * IN_F + i0 + ti];
        }
    }
    { // splines — coalesced over o
        int to = tid & 31, ti = tid >> 5;
#pragma unroll
        for (int p = 0; p < 4; ++p) {
            int il = ti + p * 8;
            int i = i0 + il;
            float scale = sc[(size_t)i * OUT_F + o0 + to];
#pragma unroll
            for (int k = 0; k < NB; ++k)
                tile[1 + k][to][il] = sw[((size_t)i * NB + k) * OUT_F + o0 + to] * scale;
        }
    }
    __syncthreads();
    { // write g_Wh[o][c*1024+i] — coalesced over i
        int il = tid & 31, ol0 = tid >> 5;
#pragma unroll
        for (int p = 0; p < 4; ++p) {
            int ol = ol0 + p * 8;
            size_t orow = (size_t)(o0 + ol) * KDIM;
#pragma unroll
            for (int c = 0; c < 9; ++c)
                g_Wh[orow + (size_t)c * IN_F + i0 + il] =
                    __float2half_rn(tile[c][ol][il]);
        }
    }
}

// ---------------------------------------------------------------------------
// prep_act — R9 v3 math (measured best) with ONE change: streaming stores
// (st.global.cs) for all 9 plane writes + streaming load of x. A is 302MB,
// write-once-read-later: bypassing L2 allocation should raise write BW.
// ---------------------------------------------------------------------------
__device__ __forceinline__ float pick_w(int j, int m, float w0, float w1,
                                        float w2, float w3) {
    int tt = j - m + 3;
    return tt == 0 ? w0 : tt == 1 ? w1 : tt == 2 ? w2 : tt == 3 ? w3 : 0.0f;
}

__global__ void prep_act(const float* __restrict__ x,
                         const float* __restrict__ grid) {
    const float t0 = __ldg(&grid[0]);
    const float invh = 11.0f / (__ldg(&grid[11]) - t0);

    int idx = (blockIdx.x * 256 + threadIdx.x) * 2;      // 2 adjacent elements
    int b = idx >> 10, i = idx & 1023;
    float2 xv2 = __ldcs((const float2*)(x + idx));
    __half* arow = g_Ah + (size_t)b * KDIM + i;

    float w0[2], w1[2], w2[2], w3[2], sl[2];
    int m[2];
#pragma unroll
    for (int e = 0; e < 2; ++e) {
        float xv = e ? xv2.y : xv2.x;
        sl[e] = __fdividef(xv, 1.0f + __expf(-xv));
        float u = (xv - t0) * invh;
        float mf = floorf(u);
        m[e] = (int)mf;
        float f = u - mf;
        float f2 = f * f, f3 = f2 * f;
        w3[e] = f3 * (1.0f / 6.0f);
        w0[e] = (1.0f / 6.0f) - 0.5f * f + 0.5f * f2 - w3[e];
        w1[e] = 0.5f * f3 - f2 + (2.0f / 3.0f);
        w2[e] = -0.5f * f3 + 0.5f * f2 + 0.5f * f + (1.0f / 6.0f);
    }

    __stcs((__half2*)arow, __floats2half2_rn(sl[0], sl[1]));
#pragma unroll
    for (int j = 0; j < 8; ++j) {
        float v0 = pick_w(j, m[0], w0[0], w1[0], w2[0], w3[0]);
        float v1 = pick_w(j, m[1], w0[1], w1[1], w2[1], w3[1]);
        __stcs((__half2*)(arow + (size_t)(1 + j) * IN_F),
               __floats2half2_rn(v0, v1));
    }
}

// ---------------------------------------------------------------------------
// fp16 GEMM — EXACT R12 (measured best, GEMM ~388us): BK=128 (72 iters),
// STAGES=2, CTA 128x256, 512 thr (16 warps, warp 64x32), SW128 smem,
// ldmatrix x4 for A / 4x ldsm x2 for B (x4-paired B measured WORSE in R13),
// mma.m16n8k16 f32 accum.
// ---------------------------------------------------------------------------
#define BM 128
#define BN 256
#define BK 128
#define KITERS (KDIM / BK)        // 72
#define STAGES 2
#define A_SUB (BM * 128)          // 16384 bytes per 64-k A sub-tile
#define B_SUB (BN * 128)          // 32768 bytes per 64-k B sub-tile
#define A_BYTES (2 * A_SUB)       // 32768
#define B_BYTES (2 * B_SUB)       // 65536
#define STG_BYTES (A_BYTES + B_BYTES)          // 98304
#define GEMM_SMEM (STAGES * STG_BYTES)         // 196608

__device__ __forceinline__ uint32_t smem_u32(const void* p) {
    uint32_t a;
    asm("{ .reg .u64 t; cvta.to.shared.u64 t, %1; cvt.u32.u64 %0, t; }" : "=r"(a) : "l"(p));
    return a;
}
__device__ __forceinline__ void cp16(uint32_t dst, const void* src) {
    asm volatile("cp.async.cg.shared.global [%0], [%1], 16;\n" :: "r"(dst), "l"(src));
}
__device__ __forceinline__ void ldsm_x4(uint32_t* r, uint32_t addr) {
    asm volatile("ldmatrix.sync.aligned.m8n8.x4.shared.b16 {%0,%1,%2,%3}, [%4];"
                 : "=r"(r[0]), "=r"(r[1]), "=r"(r[2]), "=r"(r[3]) : "r"(addr));
}
__device__ __forceinline__ void ldsm_x2(uint32_t* r, uint32_t addr) {
    asm volatile("ldmatrix.sync.aligned.m8n8.x2.shared.b16 {%0,%1}, [%2];"
                 : "=r"(r[0]), "=r"(r[1]) : "r"(addr));
}
__device__ __forceinline__ void mma_f16(float* c, const uint32_t* a, const uint32_t* b) {
    asm volatile(
        "mma.sync.aligned.m16n8k16.row.col.f32.f16.f16.f32 "
        "{%0,%1,%2,%3}, {%4,%5,%6,%7}, {%8,%9}, {%0,%1,%2,%3};\n"
        : "+f"(c[0]), "+f"(c[1]), "+f"(c[2]), "+f"(c[3])
        : "r"(a[0]), "r"(a[1]), "r"(a[2]), "r"(a[3]), "r"(b[0]), "r"(b[1]));
}

// Loads one 128-k stage = two 64-k sub-tiles for A and B.
__device__ __forceinline__ void load_stage(uint32_t sbase, int slot,
                                           int m0, int n0, int k0, int tid) {
    uint32_t sd = sbase + slot * STG_BYTES;
#pragma unroll
    for (int h = 0; h < 2; ++h) {              // A sub-tiles
        uint32_t sda = sd + h * A_SUB;
        int kh = k0 + h * 64;
#pragma unroll
        for (int t = 0; t < 2; ++t) {          // 1024 chunks of 16B
            int idx = tid + t * 512;
            int row = idx >> 3, c = idx & 7;
            cp16(sda + row * 128 + ((c ^ (row & 7)) << 4),
                 g_Ah + (size_t)(m0 + row) * KDIM + kh + c * 8);
        }
    }
    uint32_t sdb = sd + A_BYTES;
#pragma unroll
    for (int h = 0; h < 2; ++h) {              // B sub-tiles
        uint32_t sdbh = sdb + h * B_SUB;
        int kh = k0 + h * 64;
#pragma unroll
        for (int t = 0; t < 4; ++t) {          // 2048 chunks of 16B
            int idx = tid + t * 512;
            int row = idx >> 3, c = idx & 7;
            cp16(sdbh + row * 128 + ((c ^ (row & 7)) << 4),
                 g_Wh + (size_t)(n0 + row) * KDIM + kh + c * 8);
        }
    }
}

__global__ void __launch_bounds__(512, 1)
kan_gemm(float* __restrict__ C) {
    extern __shared__ char smem[];
    const uint32_t sbase = smem_u32(smem);

    const int tid = threadIdx.x;
    const int warp = tid >> 5, lane = tid & 31;
    const int wm = warp & 1;          // 2 m-warps   -> 64 rows each
    const int wn = warp >> 1;         // 8 n-warps   -> 32 cols each
    const int g = lane >> 2, tg = lane & 3;
    const int m0 = blockIdx.y * BM;
    const int n0 = blockIdx.x * BN;

    // Per-lane ldmatrix address components
    int a_row[4], b_row[4];
    const int a_kt = lane >> 4;               // A: ktile select (x4 layout)
    const int b_kt = (lane >> 3) & 1;         // B: ktile select (x2 layout)
#pragma unroll
    for (int mt = 0; mt < 4; ++mt) a_row[mt] = wm * 64 + mt * 16 + (lane & 15);
#pragma unroll
    for (int nt = 0; nt < 4; ++nt) b_row[nt] = wn * 32 + nt * 8 + (lane & 7);

    float acc[4][4][4];
#pragma unroll
    for (int a = 0; a < 4; ++a)
#pragma unroll
        for (int b = 0; b < 4; ++b)
#pragma unroll
            for (int c = 0; c < 4; ++c) acc[a][b][c] = 0.0f;

    // Prologue: stage 0
    load_stage(sbase, 0, m0, n0, 0, tid);
    asm volatile("cp.async.commit_group;\n" ::);

    for (int it = 0; it < KITERS; ++it) {
        asm volatile("cp.async.wait_group 0;\n" ::);
        __syncthreads();

        if (it + 1 < KITERS)
            load_stage(sbase, (it + 1) & 1, m0, n0, (it + 1) * BK, tid);
        asm volatile("cp.async.commit_group;\n" ::);

        const uint32_t sa = sbase + (it & 1) * STG_BYTES;
        const uint32_t sb = sa + A_BYTES;

#pragma unroll
        for (int kk = 0; kk < BK / 16; ++kk) {      // 8 k-chunks; sub-tile = kk>>2
            const uint32_t sah = sa + (kk >> 2) * A_SUB;
            const uint32_t sbh = sb + (kk >> 2) * B_SUB;
            const int kk2 = kk & 3;
            uint32_t af[4][4], bf[4][2];
#pragma unroll
            for (int mt = 0; mt < 4; ++mt) {
                int r = a_row[mt];
                ldsm_x4(af[mt], sah + r * 128 + (((kk2 * 2 + a_kt) ^ (r & 7)) << 4));
            }
#pragma unroll
            for (int nt = 0; nt < 4; ++nt) {
                int r = b_row[nt];
                ldsm_x2(bf[nt], sbh + r * 128 + (((kk2 * 2 + b_kt) ^ (r & 7)) << 4));
            }
#pragma unroll
            for (int mt = 0; mt < 4; ++mt)
#pragma unroll
                for (int nt = 0; nt < 4; ++nt)
                    mma_f16(acc[mt][nt], af[mt], bf[nt]);
        }
    }

    // Epilogue
#pragma unroll
    for (int mt = 0; mt < 4; ++mt) {
        int r0 = m0 + wm * 64 + mt * 16 + g;
#pragma unroll
        for (int nt = 0; nt < 4; ++nt) {
            int col = n0 + wn * 32 + nt * 8 + 2 * tg;
            *(float2*)(C + (size_t)r0 * OUT_F + col) =
                make_float2(acc[mt][nt][0], acc[mt][nt][1]);
            *(float2*)(C + (size_t)(r0 + 8) * OUT_F + col) =
                make_float2(acc[mt][nt][2], acc[mt][nt][3]);
        }
    }
}

// ---------------------------------------------------------------------------
extern "C" void kernel_launch(void* const* d_in, const int* in_sizes, int n_in,
                              void* d_out, int out_size) {
    const float* x    = (const float*)d_in[0];
    const float* grid = (const float*)d_in[1];
    const float* bw   = (const float*)d_in[2];
    const float* sw   = (const float*)d_in[3];
    const float* sc   = (const float*)d_in[4];
    float* out = (float*)d_out;

    prep_w<<<1024, 256>>>(bw, sw, sc);
    prep_act<<<(BATCH * IN_F) / 512, 256>>>(x, grid);

    cudaFuncSetAttribute(kan_gemm, cudaFuncAttributeMaxDynamicSharedMemorySize, GEMM_SMEM);
    dim3 grd(OUT_F / BN, BATCH / BM);   // 4 x 64 = 256 CTAs
    kan_gemm<<<grd, 512, GEMM_SMEM>>>(out);
}

// round 15
// speedup vs baseline: 1.1596x; 1.0157x over previous
#include <cuda_runtime.h>
#include <cuda_fp16.h>
#include <cstdint>
#include <math.h>

#define BATCH 8192
#define IN_F  1024
#define OUT_F 1024
#define NB    8
#define KDIM  (IN_F * 9)          // 9216

// Scratch (__device__ globals — sanctioned)
__device__ __half g_Ah[(size_t)BATCH * KDIM];   // [b][c*1024+i]
__device__ __half g_Wh[(size_t)OUT_F * KDIM];   // [o][c*1024+i]  (B as [N,K])

// ---------------------------------------------------------------------------
// prep_w: augmented weights, transposed to [OUT_F, KDIM], fp16. (14us measured)
// ---------------------------------------------------------------------------
__global__ void prep_w(const float* __restrict__ bw,
                       const float* __restrict__ sw,
                       const float* __restrict__ sc) {
    __shared__ float tile[9][32][33];
    const int i0 = (blockIdx.x & 31) * 32;
    const int o0 = (blockIdx.x >> 5) * 32;
    const int tid = threadIdx.x;                 // 256

    { // c = 0 : base_weight[o, i] — coalesced over i
        int ti = tid & 31, to = tid >> 5;
#pragma unroll
        for (int p = 0; p < 4; ++p) {
            int ol = to + p * 8;
            tile[0][ol][ti] = bw[(size_t)(o0 + ol) * IN_F + i0 + ti];
        }
    }
    { // splines — coalesced over o
        int to = tid & 31, ti = tid >> 5;
#pragma unroll
        for (int p = 0; p < 4; ++p) {
            int il = ti + p * 8;
            int i = i0 + il;
            float scale = sc[(size_t)i * OUT_F + o0 + to];
#pragma unroll
            for (int k = 0; k < NB; ++k)
                tile[1 + k][to][il] = sw[((size_t)i * NB + k) * OUT_F + o0 + to] * scale;
        }
    }
    __syncthreads();
    { // write g_Wh[o][c*1024+i] — coalesced over i
        int il = tid & 31, ol0 = tid >> 5;
#pragma unroll
        for (int p = 0; p < 4; ++p) {
            int ol = ol0 + p * 8;
            size_t orow = (size_t)(o0 + ol) * KDIM;
#pragma unroll
            for (int c = 0; c < 9; ++c)
                g_Wh[orow + (size_t)c * IN_F + i0 + il] =
                    __float2half_rn(tile[c][ol][il]);
        }
    }
}

// ---------------------------------------------------------------------------
// prep_act — EXACT R9/R12 best (~90us): uniform-knot closed form,
// 2 elements/thread, fully coalesced half2 stores, zeros explicit.
// ---------------------------------------------------------------------------
__device__ __forceinline__ float pick_w(int j, int m, float w0, float w1,
                                        float w2, float w3) {
    int tt = j - m + 3;
    return tt == 0 ? w0 : tt == 1 ? w1 : tt == 2 ? w2 : tt == 3 ? w3 : 0.0f;
}

__global__ void prep_act(const float* __restrict__ x,
                         const float* __restrict__ grid) {
    const float t0 = __ldg(&grid[0]);
    const float invh = 11.0f / (__ldg(&grid[11]) - t0);

    int idx = (blockIdx.x * 256 + threadIdx.x) * 2;      // 2 adjacent elements
    int b = idx >> 10, i = idx & 1023;
    float2 xv2 = *(const float2*)(x + idx);
    __half* arow = g_Ah + (size_t)b * KDIM + i;

    float w0[2], w1[2], w2[2], w3[2], sl[2];
    int m[2];
#pragma unroll
    for (int e = 0; e < 2; ++e) {
        float xv = e ? xv2.y : xv2.x;
        sl[e] = __fdividef(xv, 1.0f + __expf(-xv));
        float u = (xv - t0) * invh;
        float mf = floorf(u);
        m[e] = (int)mf;
        float f = u - mf;
        float f2 = f * f, f3 = f2 * f;
        w3[e] = f3 * (1.0f / 6.0f);
        w0[e] = (1.0f / 6.0f) - 0.5f * f + 0.5f * f2 - w3[e];
        w1[e] = 0.5f * f3 - f2 + (2.0f / 3.0f);
        w2[e] = -0.5f * f3 + 0.5f * f2 + 0.5f * f + (1.0f / 6.0f);
    }

    *(__half2*)arow = __floats2half2_rn(sl[0], sl[1]);
#pragma unroll
    for (int j = 0; j < 8; ++j) {
        float v0 = pick_w(j, m[0], w0[0], w1[0], w2[0], w3[0]);
        float v1 = pick_w(j, m[1], w0[1], w1[1], w2[1], w3[1]);
        *(__half2*)(arow + (size_t)(1 + j) * IN_F) = __floats2half2_rn(v0, v1);
    }
}

// ---------------------------------------------------------------------------
// fp16 GEMM — R12 (measured best, GEMM ~388us) + ONE change: #pragma unroll 2
// on the main K loop (compile-time slot specialization, cross-iter schedule).
// BK=128 (72 iters), STAGES=2, CTA 128x256, 512 thr (16 warps, warp 64x32),
// SW128 smem, ldmatrix x4 A / 4x ldsm x2 B, mma.m16n8k16 f32 accum.
// ---------------------------------------------------------------------------
#define BM 128
#define BN 256
#define BK 128
#define KITERS (KDIM / BK)        // 72
#define STAGES 2
#define A_SUB (BM * 128)          // 16384 bytes per 64-k A sub-tile
#define B_SUB (BN * 128)          // 32768 bytes per 64-k B sub-tile
#define A_BYTES (2 * A_SUB)       // 32768
#define B_BYTES (2 * B_SUB)       // 65536
#define STG_BYTES (A_BYTES + B_BYTES)          // 98304
#define GEMM_SMEM (STAGES * STG_BYTES)         // 196608

__device__ __forceinline__ uint32_t smem_u32(const void* p) {
    uint32_t a;
    asm("{ .reg .u64 t; cvta.to.shared.u64 t, %1; cvt.u32.u64 %0, t; }" : "=r"(a) : "l"(p));
    return a;
}
__device__ __forceinline__ void cp16(uint32_t dst, const void* src) {
    asm volatile("cp.async.cg.shared.global [%0], [%1], 16;\n" :: "r"(dst), "l"(src));
}
__device__ __forceinline__ void ldsm_x4(uint32_t* r, uint32_t addr) {
    asm volatile("ldmatrix.sync.aligned.m8n8.x4.shared.b16 {%0,%1,%2,%3}, [%4];"
                 : "=r"(r[0]), "=r"(r[1]), "=r"(r[2]), "=r"(r[3]) : "r"(addr));
}
__device__ __forceinline__ void ldsm_x2(uint32_t* r, uint32_t addr) {
    asm volatile("ldmatrix.sync.aligned.m8n8.x2.shared.b16 {%0,%1}, [%2];"
                 : "=r"(r[0]), "=r"(r[1]) : "r"(addr));
}
__device__ __forceinline__ void mma_f16(float* c, const uint32_t* a, const uint32_t* b) {
    asm volatile(
        "mma.sync.aligned.m16n8k16.row.col.f32.f16.f16.f32 "
        "{%0,%1,%2,%3}, {%4,%5,%6,%7}, {%8,%9}, {%0,%1,%2,%3};\n"
        : "+f"(c[0]), "+f"(c[1]), "+f"(c[2]), "+f"(c[3])
        : "r"(a[0]), "r"(a[1]), "r"(a[2]), "r"(a[3]), "r"(b[0]), "r"(b[1]));
}

// Loads one 128-k stage = two 64-k sub-tiles for A and B.
__device__ __forceinline__ void load_stage(uint32_t sbase, int slot,
                                           int m0, int n0, int k0, int tid) {
    uint32_t sd = sbase + slot * STG_BYTES;
#pragma unroll
    for (int h = 0; h < 2; ++h) {              // A sub-tiles
        uint32_t sda = sd + h * A_SUB;
        int kh = k0 + h * 64;
#pragma unroll
        for (int t = 0; t < 2; ++t) {          // 1024 chunks of 16B
            int idx = tid + t * 512;
            int row = idx >> 3, c = idx & 7;
            cp16(sda + row * 128 + ((c ^ (row & 7)) << 4),
                 g_Ah + (size_t)(m0 + row) * KDIM + kh + c * 8);
        }
    }
    uint32_t sdb = sd + A_BYTES;
#pragma unroll
    for (int h = 0; h < 2; ++h) {              // B sub-tiles
        uint32_t sdbh = sdb + h * B_SUB;
        int kh = k0 + h * 64;
#pragma unroll
        for (int t = 0; t < 4; ++t) {          // 2048 chunks of 16B
            int idx = tid + t * 512;
            int row = idx >> 3, c = idx & 7;
            cp16(sdbh + row * 128 + ((c ^ (row & 7)) << 4),
                 g_Wh + (size_t)(n0 + row) * KDIM + kh + c * 8);
        }
    }
}

__global__ void __launch_bounds__(512, 1)
kan_gemm(float* __restrict__ C) {
    extern __shared__ char smem[];
    const uint32_t sbase = smem_u32(smem);

    const int tid = threadIdx.x;
    const int warp = tid >> 5, lane = tid & 31;
    const int wm = warp & 1;          // 2 m-warps   -> 64 rows each
    const int wn = warp >> 1;         // 8 n-warps   -> 32 cols each
    const int g = lane >> 2, tg = lane & 3;
    const int m0 = blockIdx.y * BM;
    const int n0 = blockIdx.x * BN;

    // Per-lane ldmatrix address components
    int a_row[4], b_row[4];
    const int a_kt = lane >> 4;               // A: ktile select (x4 layout)
    const int b_kt = (lane >> 3) & 1;         // B: ktile select (x2 layout)
#pragma unroll
    for (int mt = 0; mt < 4; ++mt) a_row[mt] = wm * 64 + mt * 16 + (lane & 15);
#pragma unroll
    for (int nt = 0; nt < 4; ++nt) b_row[nt] = wn * 32 + nt * 8 + (lane & 7);

    float acc[4][4][4];
#pragma unroll
    for (int a = 0; a < 4; ++a)
#pragma unroll
        for (int b = 0; b < 4; ++b)
#pragma unroll
            for (int c = 0; c < 4; ++c) acc[a][b][c] = 0.0f;

    // Prologue: stage 0
    load_stage(sbase, 0, m0, n0, 0, tid);
    asm volatile("cp.async.commit_group;\n" ::);

#pragma unroll 2
    for (int it = 0; it < KITERS; ++it) {
        asm volatile("cp.async.wait_group 0;\n" ::);
        __syncthreads();

        if (it + 1 < KITERS)
            load_stage(sbase, (it + 1) & 1, m0, n0, (it + 1) * BK, tid);
        asm volatile("cp.async.commit_group;\n" ::);

        const uint32_t sa = sbase + (it & 1) * STG_BYTES;
        const uint32_t sb = sa + A_BYTES;

#pragma unroll
        for (int kk = 0; kk < BK / 16; ++kk) {      // 8 k-chunks; sub-tile = kk>>2
            const uint32_t sah = sa + (kk >> 2) * A_SUB;
            const uint32_t sbh = sb + (kk >> 2) * B_SUB;
            const int kk2 = kk & 3;
            uint32_t af[4][4], bf[4][2];
#pragma unroll
            for (int mt = 0; mt < 4; ++mt) {
                int r = a_row[mt];
                ldsm_x4(af[mt], sah + r * 128 + (((kk2 * 2 + a_kt) ^ (r & 7)) << 4));
            }
#pragma unroll
            for (int nt = 0; nt < 4; ++nt) {
                int r = b_row[nt];
                ldsm_x2(bf[nt], sbh + r * 128 + (((kk2 * 2 + b_kt) ^ (r & 7)) << 4));
            }
#pragma unroll
            for (int mt = 0; mt < 4; ++mt)
#pragma unroll
                for (int nt = 0; nt < 4; ++nt)
                    mma_f16(acc[mt][nt], af[mt], bf[nt]);
        }
    }

    // Epilogue
#pragma unroll
    for (int mt = 0; mt < 4; ++mt) {
        int r0 = m0 + wm * 64 + mt * 16 + g;
#pragma unroll
        for (int nt = 0; nt < 4; ++nt) {
            int col = n0 + wn * 32 + nt * 8 + 2 * tg;
            *(float2*)(C + (size_t)r0 * OUT_F + col) =
                make_float2(acc[mt][nt][0], acc[mt][nt][1]);
            *(float2*)(C + (size_t)(r0 + 8) * OUT_F + col) =
                make_float2(acc[mt][nt][2], acc[mt][nt][3]);
        }
    }
}

// ---------------------------------------------------------------------------
extern "C" void kernel_launch(void* const* d_in, const int* in_sizes, int n_in,
                              void* d_out, int out_size) {
    const float* x    = (const float*)d_in[0];
    const float* grid = (const float*)d_in[1];
    const float* bw   = (const float*)d_in[2];
    const float* sw   = (const float*)d_in[3];
    const float* sc   = (const float*)d_in[4];
    float* out = (float*)d_out;

    prep_w<<<1024, 256>>>(bw, sw, sc);
    prep_act<<<(BATCH * IN_F) / 512, 256>>>(x, grid);

    cudaFuncSetAttribute(kan_gemm, cudaFuncAttributeMaxDynamicSharedMemorySize, GEMM_SMEM);
    dim3 grd(OUT_F / BN, BATCH / BM);   // 4 x 64 = 256 CTAs
    kan_gemm<<<grd, 512, GEMM_SMEM>>>(out);
}

// round 16
// speedup vs baseline: 1.2061x; 1.0401x over previous
#include <cuda_runtime.h>
#include <cuda_fp16.h>
#include <cstdint>
#include <math.h>

#define BATCH 8192
#define IN_F  1024
#define OUT_F 1024
#define NB    8
#define KDIM  (IN_F * 9)          // 9216

// Scratch (__device__ globals — sanctioned)
__device__ __half g_Ah[(size_t)BATCH * KDIM];   // [b][c*1024+i]
__device__ __half g_Wh[(size_t)OUT_F * KDIM];   // [o][c*1024+i]  (B as [N,K])

// ---------------------------------------------------------------------------
// prep_w: augmented weights, transposed to [OUT_F, KDIM], fp16. (14us measured)
// ---------------------------------------------------------------------------
__global__ void prep_w(const float* __restrict__ bw,
                       const float* __restrict__ sw,
                       const float* __restrict__ sc) {
    __shared__ float tile[9][32][33];
    const int i0 = (blockIdx.x & 31) * 32;
    const int o0 = (blockIdx.x >> 5) * 32;
    const int tid = threadIdx.x;                 // 256

    { // c = 0 : base_weight[o, i] — coalesced over i
        int ti = tid & 31, to = tid >> 5;
#pragma unroll
        for (int p = 0; p < 4; ++p) {
            int ol = to + p * 8;
            tile[0][ol][ti] = bw[(size_t)(o0 + ol) * IN_F + i0 + ti];
        }
    }
    { // splines — coalesced over o
        int to = tid & 31, ti = tid >> 5;
#pragma unroll
        for (int p = 0; p < 4; ++p) {
            int il = ti + p * 8;
            int i = i0 + il;
            float scale = sc[(size_t)i * OUT_F + o0 + to];
#pragma unroll
            for (int k = 0; k < NB; ++k)
                tile[1 + k][to][il] = sw[((size_t)i * NB + k) * OUT_F + o0 + to] * scale;
        }
    }
    __syncthreads();
    { // write g_Wh[o][c*1024+i] — coalesced over i
        int il = tid & 31, ol0 = tid >> 5;
#pragma unroll
        for (int p = 0; p < 4; ++p) {
            int ol = ol0 + p * 8;
            size_t orow = (size_t)(o0 + ol) * KDIM;
#pragma unroll
            for (int c = 0; c < 9; ++c)
                g_Wh[orow + (size_t)c * IN_F + i0 + il] =
                    __float2half_rn(tile[c][ol][il]);
        }
    }
}

// ---------------------------------------------------------------------------
// prep_act — EXACT measured best (~90us): uniform-knot closed form,
// 2 elements/thread, fully coalesced half2 stores, zeros explicit.
// ---------------------------------------------------------------------------
__device__ __forceinline__ float pick_w(int j, int m, float w0, float w1,
                                        float w2, float w3) {
    int tt = j - m + 3;
    return tt == 0 ? w0 : tt == 1 ? w1 : tt == 2 ? w2 : tt == 3 ? w3 : 0.0f;
}

__global__ void prep_act(const float* __restrict__ x,
                         const float* __restrict__ grid) {
    const float t0 = __ldg(&grid[0]);
    const float invh = 11.0f / (__ldg(&grid[11]) - t0);

    int idx = (blockIdx.x * 256 + threadIdx.x) * 2;      // 2 adjacent elements
    int b = idx >> 10, i = idx & 1023;
    float2 xv2 = *(const float2*)(x + idx);
    __half* arow = g_Ah + (size_t)b * KDIM + i;

    float w0[2], w1[2], w2[2], w3[2], sl[2];
    int m[2];
#pragma unroll
    for (int e = 0; e < 2; ++e) {
        float xv = e ? xv2.y : xv2.x;
        sl[e] = __fdividef(xv, 1.0f + __expf(-xv));
        float u = (xv - t0) * invh;
        float mf = floorf(u);
        m[e] = (int)mf;
        float f = u - mf;
        float f2 = f * f, f3 = f2 * f;
        w3[e] = f3 * (1.0f / 6.0f);
        w0[e] = (1.0f / 6.0f) - 0.5f * f + 0.5f * f2 - w3[e];
        w1[e] = 0.5f * f3 - f2 + (2.0f / 3.0f);
        w2[e] = -0.5f * f3 + 0.5f * f2 + 0.5f * f + (1.0f / 6.0f);
    }

    *(__half2*)arow = __floats2half2_rn(sl[0], sl[1]);
#pragma unroll
    for (int j = 0; j < 8; ++j) {
        float v0 = pick_w(j, m[0], w0[0], w1[0], w2[0], w3[0]);
        float v1 = pick_w(j, m[1], w0[1], w1[1], w2[1], w3[1]);
        *(__half2*)(arow + (size_t)(1 + j) * IN_F) = __floats2half2_rn(v0, v1);
    }
}

// ---------------------------------------------------------------------------
// fp16 GEMM — R15 config (measured best) with ONE change: K-loop unroll 2->4.
// BK=128 (72 iters), STAGES=2, CTA 128x256, 512 thr (16 warps, warp 64x32),
// SW128 smem, ldmatrix x4 A / 4x ldsm x2 B, mma.m16n8k16 f32 accum.
// ---------------------------------------------------------------------------
#define BM 128
#define BN 256
#define BK 128
#define KITERS (KDIM / BK)        // 72
#define STAGES 2
#define A_SUB (BM * 128)          // 16384 bytes per 64-k A sub-tile
#define B_SUB (BN * 128)          // 32768 bytes per 64-k B sub-tile
#define A_BYTES (2 * A_SUB)       // 32768
#define B_BYTES (2 * B_SUB)       // 65536
#define STG_BYTES (A_BYTES + B_BYTES)          // 98304
#define GEMM_SMEM (STAGES * STG_BYTES)         // 196608

__device__ __forceinline__ uint32_t smem_u32(const void* p) {
    uint32_t a;
    asm("{ .reg .u64 t; cvta.to.shared.u64 t, %1; cvt.u32.u64 %0, t; }" : "=r"(a) : "l"(p));
    return a;
}
__device__ __forceinline__ void cp16(uint32_t dst, const void* src) {
    asm volatile("cp.async.cg.shared.global [%0], [%1], 16;\n" :: "r"(dst), "l"(src));
}
__device__ __forceinline__ void ldsm_x4(uint32_t* r, uint32_t addr) {
    asm volatile("ldmatrix.sync.aligned.m8n8.x4.shared.b16 {%0,%1,%2,%3}, [%4];"
                 : "=r"(r[0]), "=r"(r[1]), "=r"(r[2]), "=r"(r[3]) : "r"(addr));
}
__device__ __forceinline__ void ldsm_x2(uint32_t* r, uint32_t addr) {
    asm volatile("ldmatrix.sync.aligned.m8n8.x2.shared.b16 {%0,%1}, [%2];"
                 : "=r"(r[0]), "=r"(r[1]) : "r"(addr));
}
__device__ __forceinline__ void mma_f16(float* c, const uint32_t* a, const uint32_t* b) {
    asm volatile(
        "mma.sync.aligned.m16n8k16.row.col.f32.f16.f16.f32 "
        "{%0,%1,%2,%3}, {%4,%5,%6,%7}, {%8,%9}, {%0,%1,%2,%3};\n"
        : "+f"(c[0]), "+f"(c[1]), "+f"(c[2]), "+f"(c[3])
        : "r"(a[0]), "r"(a[1]), "r"(a[2]), "r"(a[3]), "r"(b[0]), "r"(b[1]));
}

// Loads one 128-k stage = two 64-k sub-tiles for A and B.
__device__ __forceinline__ void load_stage(uint32_t sbase, int slot,
                                           int m0, int n0, int k0, int tid) {
    uint32_t sd = sbase + slot * STG_BYTES;
#pragma unroll
    for (int h = 0; h < 2; ++h) {              // A sub-tiles
        uint32_t sda = sd + h * A_SUB;
        int kh = k0 + h * 64;
#pragma unroll
        for (int t = 0; t < 2; ++t) {          // 1024 chunks of 16B
            int idx = tid + t * 512;
            int row = idx >> 3, c = idx & 7;
            cp16(sda + row * 128 + ((c ^ (row & 7)) << 4),
                 g_Ah + (size_t)(m0 + row) * KDIM + kh + c * 8);
        }
    }
    uint32_t sdb = sd + A_BYTES;
#pragma unroll
    for (int h = 0; h < 2; ++h) {              // B sub-tiles
        uint32_t sdbh = sdb + h * B_SUB;
        int kh = k0 + h * 64;
#pragma unroll
        for (int t = 0; t < 4; ++t) {          // 2048 chunks of 16B
            int idx = tid + t * 512;
            int row = idx >> 3, c = idx & 7;
            cp16(sdbh + row * 128 + ((c ^ (row & 7)) << 4),
                 g_Wh + (size_t)(n0 + row) * KDIM + kh + c * 8);
        }
    }
}

__global__ void __launch_bounds__(512, 1)
kan_gemm(float* __restrict__ C) {
    extern __shared__ char smem[];
    const uint32_t sbase = smem_u32(smem);

    const int tid = threadIdx.x;
    const int warp = tid >> 5, lane = tid & 31;
    const int wm = warp & 1;          // 2 m-warps   -> 64 rows each
    const int wn = warp >> 1;         // 8 n-warps   -> 32 cols each
    const int g = lane >> 2, tg = lane & 3;
    const int m0 = blockIdx.y * BM;
    const int n0 = blockIdx.x * BN;

    // Per-lane ldmatrix address components
    int a_row[4], b_row[4];
    const int a_kt = lane >> 4;               // A: ktile select (x4 layout)
    const int b_kt = (lane >> 3) & 1;         // B: ktile select (x2 layout)
#pragma unroll
    for (int mt = 0; mt < 4; ++mt) a_row[mt] = wm * 64 + mt * 16 + (lane & 15);
#pragma unroll
    for (int nt = 0; nt < 4; ++nt) b_row[nt] = wn * 32 + nt * 8 + (lane & 7);

    float acc[4][4][4];
#pragma unroll
    for (int a = 0; a < 4; ++a)
#pragma unroll
        for (int b = 0; b < 4; ++b)
#pragma unroll
            for (int c = 0; c < 4; ++c) acc[a][b][c] = 0.0f;

    // Prologue: stage 0
    load_stage(sbase, 0, m0, n0, 0, tid);
    asm volatile("cp.async.commit_group;\n" ::);

#pragma unroll 4
    for (int it = 0; it < KITERS; ++it) {
        asm volatile("cp.async.wait_group 0;\n" ::);
        __syncthreads();

        if (it + 1 < KITERS)
            load_stage(sbase, (it + 1) & 1, m0, n0, (it + 1) * BK, tid);
        asm volatile("cp.async.commit_group;\n" ::);

        const uint32_t sa = sbase + (it & 1) * STG_BYTES;
        const uint32_t sb = sa + A_BYTES;

#pragma unroll
        for (int kk = 0; kk < BK / 16; ++kk) {      // 8 k-chunks; sub-tile = kk>>2
            const uint32_t sah = sa + (kk >> 2) * A_SUB;
            const uint32_t sbh = sb + (kk >> 2) * B_SUB;
            const int kk2 = kk & 3;
            uint32_t af[4][4], bf[4][2];
#pragma unroll
            for (int mt = 0; mt < 4; ++mt) {
                int r = a_row[mt];
                ldsm_x4(af[mt], sah + r * 128 + (((kk2 * 2 + a_kt) ^ (r & 7)) << 4));
            }
#pragma unroll
            for (int nt = 0; nt < 4; ++nt) {
                int r = b_row[nt];
                ldsm_x2(bf[nt], sbh + r * 128 + (((kk2 * 2 + b_kt) ^ (r & 7)) << 4));
            }
#pragma unroll
            for (int mt = 0; mt < 4; ++mt)
#pragma unroll
                for (int nt = 0; nt < 4; ++nt)
                    mma_f16(acc[mt][nt], af[mt], bf[nt]);
        }
    }

    // Epilogue
#pragma unroll
    for (int mt = 0; mt < 4; ++mt) {
        int r0 = m0 + wm * 64 + mt * 16 + g;
#pragma unroll
        for (int nt = 0; nt < 4; ++nt) {
            int col = n0 + wn * 32 + nt * 8 + 2 * tg;
            *(float2*)(C + (size_t)r0 * OUT_F + col) =
                make_float2(acc[mt][nt][0], acc[mt][nt][1]);
            *(float2*)(C + (size_t)(r0 + 8) * OUT_F + col) =
                make_float2(acc[mt][nt][2], acc[mt][nt][3]);
        }
    }
}

// ---------------------------------------------------------------------------
extern "C" void kernel_launch(void* const* d_in, const int* in_sizes, int n_in,
                              void* d_out, int out_size) {
    const float* x    = (const float*)d_in[0];
    const float* grid = (const float*)d_in[1];
    const float* bw   = (const float*)d_in[2];
    const float* sw   = (const float*)d_in[3];
    const float* sc   = (const float*)d_in[4];
    float* out = (float*)d_out;

    prep_w<<<1024, 256>>>(bw, sw, sc);
    prep_act<<<(BATCH * IN_F) / 512, 256>>>(x, grid);

    cudaFuncSetAttribute(kan_gemm, cudaFuncAttributeMaxDynamicSharedMemorySize, GEMM_SMEM);
    dim3 grd(OUT_F / BN, BATCH / BM);   // 4 x 64 = 256 CTAs
    kan_gemm<<<grd, 512, GEMM_SMEM>>>(out);
}

// round 17
// speedup vs baseline: 1.2257x; 1.0163x over previous
#include <cuda_runtime.h>
#include <cuda_fp16.h>
#include <cstdint>
#include <math.h>

#define BATCH 8192
#define IN_F  1024
#define OUT_F 1024
#define NB    8
#define KDIM  (IN_F * 9)          // 9216

// Scratch (__device__ globals — sanctioned)
__device__ __half g_Ah[(size_t)BATCH * KDIM];   // [b][c*1024+i]
__device__ __half g_Wh[(size_t)OUT_F * KDIM];   // [o][c*1024+i]  (B as [N,K])

// ---------------------------------------------------------------------------
// prep_w: augmented weights, transposed to [OUT_F, KDIM], fp16. (14us measured)
// ---------------------------------------------------------------------------
__global__ void prep_w(const float* __restrict__ bw,
                       const float* __restrict__ sw,
                       const float* __restrict__ sc) {
    __shared__ float tile[9][32][33];
    const int i0 = (blockIdx.x & 31) * 32;
    const int o0 = (blockIdx.x >> 5) * 32;
    const int tid = threadIdx.x;                 // 256

    { // c = 0 : base_weight[o, i] — coalesced over i
        int ti = tid & 31, to = tid >> 5;
#pragma unroll
        for (int p = 0; p < 4; ++p) {
            int ol = to + p * 8;
            tile[0][ol][ti] = bw[(size_t)(o0 + ol) * IN_F + i0 + ti];
        }
    }
    { // splines — coalesced over o
        int to = tid & 31, ti = tid >> 5;
#pragma unroll
        for (int p = 0; p < 4; ++p) {
            int il = ti + p * 8;
            int i = i0 + il;
            float scale = sc[(size_t)i * OUT_F + o0 + to];
#pragma unroll
            for (int k = 0; k < NB; ++k)
                tile[1 + k][to][il] = sw[((size_t)i * NB + k) * OUT_F + o0 + to] * scale;
        }
    }
    __syncthreads();
    { // write g_Wh[o][c*1024+i] — coalesced over i
        int il = tid & 31, ol0 = tid >> 5;
#pragma unroll
        for (int p = 0; p < 4; ++p) {
            int ol = ol0 + p * 8;
            size_t orow = (size_t)(o0 + ol) * KDIM;
#pragma unroll
            for (int c = 0; c < 9; ++c)
                g_Wh[orow + (size_t)c * IN_F + i0 + il] =
                    __float2half_rn(tile[c][ol][il]);
        }
    }
}

// ---------------------------------------------------------------------------
// prep_act — EXACT measured best (~90us): uniform-knot closed form,
// 2 elements/thread, fully coalesced half2 stores, zeros explicit.
// ---------------------------------------------------------------------------
__device__ __forceinline__ float pick_w(int j, int m, float w0, float w1,
                                        float w2, float w3) {
    int tt = j - m + 3;
    return tt == 0 ? w0 : tt == 1 ? w1 : tt == 2 ? w2 : tt == 3 ? w3 : 0.0f;
}

__global__ void prep_act(const float* __restrict__ x,
                         const float* __restrict__ grid) {
    const float t0 = __ldg(&grid[0]);
    const float invh = 11.0f / (__ldg(&grid[11]) - t0);

    int idx = (blockIdx.x * 256 + threadIdx.x) * 2;      // 2 adjacent elements
    int b = idx >> 10, i = idx & 1023;
    float2 xv2 = *(const float2*)(x + idx);
    __half* arow = g_Ah + (size_t)b * KDIM + i;

    float w0[2], w1[2], w2[2], w3[2], sl[2];
    int m[2];
#pragma unroll
    for (int e = 0; e < 2; ++e) {
        float xv = e ? xv2.y : xv2.x;
        sl[e] = __fdividef(xv, 1.0f + __expf(-xv));
        float u = (xv - t0) * invh;
        float mf = floorf(u);
        m[e] = (int)mf;
        float f = u - mf;
        float f2 = f * f, f3 = f2 * f;
        w3[e] = f3 * (1.0f / 6.0f);
        w0[e] = (1.0f / 6.0f) - 0.5f * f + 0.5f * f2 - w3[e];
        w1[e] = 0.5f * f3 - f2 + (2.0f / 3.0f);
        w2[e] = -0.5f * f3 + 0.5f * f2 + 0.5f * f + (1.0f / 6.0f);
    }

    *(__half2*)arow = __floats2half2_rn(sl[0], sl[1]);
#pragma unroll
    for (int j = 0; j < 8; ++j) {
        float v0 = pick_w(j, m[0], w0[0], w1[0], w2[0], w3[0]);
        float v1 = pick_w(j, m[1], w0[1], w1[1], w2[1], w3[1]);
        *(__half2*)(arow + (size_t)(1 + j) * IN_F) = __floats2half2_rn(v0, v1);
    }
}

// ---------------------------------------------------------------------------
// fp16 GEMM — R16 config (measured best) with ONE change: K-loop unroll 4->8.
// BK=128 (72 iters), STAGES=2, CTA 128x256, 512 thr (16 warps, warp 64x32),
// SW128 smem, ldmatrix x4 A / 4x ldsm x2 B, mma.m16n8k16 f32 accum.
// ---------------------------------------------------------------------------
#define BM 128
#define BN 256
#define BK 128
#define KITERS (KDIM / BK)        // 72
#define STAGES 2
#define A_SUB (BM * 128)          // 16384 bytes per 64-k A sub-tile
#define B_SUB (BN * 128)          // 32768 bytes per 64-k B sub-tile
#define A_BYTES (2 * A_SUB)       // 32768
#define B_BYTES (2 * B_SUB)       // 65536
#define STG_BYTES (A_BYTES + B_BYTES)          // 98304
#define GEMM_SMEM (STAGES * STG_BYTES)         // 196608

__device__ __forceinline__ uint32_t smem_u32(const void* p) {
    uint32_t a;
    asm("{ .reg .u64 t; cvta.to.shared.u64 t, %1; cvt.u32.u64 %0, t; }" : "=r"(a) : "l"(p));
    return a;
}
__device__ __forceinline__ void cp16(uint32_t dst, const void* src) {
    asm volatile("cp.async.cg.shared.global [%0], [%1], 16;\n" :: "r"(dst), "l"(src));
}
__device__ __forceinline__ void ldsm_x4(uint32_t* r, uint32_t addr) {
    asm volatile("ldmatrix.sync.aligned.m8n8.x4.shared.b16 {%0,%1,%2,%3}, [%4];"
                 : "=r"(r[0]), "=r"(r[1]), "=r"(r[2]), "=r"(r[3]) : "r"(addr));
}
__device__ __forceinline__ void ldsm_x2(uint32_t* r, uint32_t addr) {
    asm volatile("ldmatrix.sync.aligned.m8n8.x2.shared.b16 {%0,%1}, [%2];"
                 : "=r"(r[0]), "=r"(r[1]) : "r"(addr));
}
__device__ __forceinline__ void mma_f16(float* c, const uint32_t* a, const uint32_t* b) {
    asm volatile(
        "mma.sync.aligned.m16n8k16.row.col.f32.f16.f16.f32 "
        "{%0,%1,%2,%3}, {%4,%5,%6,%7}, {%8,%9}, {%0,%1,%2,%3};\n"
        : "+f"(c[0]), "+f"(c[1]), "+f"(c[2]), "+f"(c[3])
        : "r"(a[0]), "r"(a[1]), "r"(a[2]), "r"(a[3]), "r"(b[0]), "r"(b[1]));
}

// Loads one 128-k stage = two 64-k sub-tiles for A and B.
__device__ __forceinline__ void load_stage(uint32_t sbase, int slot,
                                           int m0, int n0, int k0, int tid) {
    uint32_t sd = sbase + slot * STG_BYTES;
#pragma unroll
    for (int h = 0; h < 2; ++h) {              // A sub-tiles
        uint32_t sda = sd + h * A_SUB;
        int kh = k0 + h * 64;
#pragma unroll
        for (int t = 0; t < 2; ++t) {          // 1024 chunks of 16B
            int idx = tid + t * 512;
            int row = idx >> 3, c = idx & 7;
            cp16(sda + row * 128 + ((c ^ (row & 7)) << 4),
                 g_Ah + (size_t)(m0 + row) * KDIM + kh + c * 8);
        }
    }
    uint32_t sdb = sd + A_BYTES;
#pragma unroll
    for (int h = 0; h < 2; ++h) {              // B sub-tiles
        uint32_t sdbh = sdb + h * B_SUB;
        int kh = k0 + h * 64;
#pragma unroll
        for (int t = 0; t < 4; ++t) {          // 2048 chunks of 16B
            int idx = tid + t * 512;
            int row = idx >> 3, c = idx & 7;
            cp16(sdbh + row * 128 + ((c ^ (row & 7)) << 4),
                 g_Wh + (size_t)(n0 + row) * KDIM + kh + c * 8);
        }
    }
}

__global__ void __launch_bounds__(512, 1)
kan_gemm(float* __restrict__ C) {
    extern __shared__ char smem[];
    const uint32_t sbase = smem_u32(smem);

    const int tid = threadIdx.x;
    const int warp = tid >> 5, lane = tid & 31;
    const int wm = warp & 1;          // 2 m-warps   -> 64 rows each
    const int wn = warp >> 1;         // 8 n-warps   -> 32 cols each
    const int g = lane >> 2, tg = lane & 3;
    const int m0 = blockIdx.y * BM;
    const int n0 = blockIdx.x * BN;

    // Per-lane ldmatrix address components
    int a_row[4], b_row[4];
    const int a_kt = lane >> 4;               // A: ktile select (x4 layout)
    const int b_kt = (lane >> 3) & 1;         // B: ktile select (x2 layout)
#pragma unroll
    for (int mt = 0; mt < 4; ++mt) a_row[mt] = wm * 64 + mt * 16 + (lane & 15);
#pragma unroll
    for (int nt = 0; nt < 4; ++nt) b_row[nt] = wn * 32 + nt * 8 + (lane & 7);

    float acc[4][4][4];
#pragma unroll
    for (int a = 0; a < 4; ++a)
#pragma unroll
        for (int b = 0; b < 4; ++b)
#pragma unroll
            for (int c = 0; c < 4; ++c) acc[a][b][c] = 0.0f;

    // Prologue: stage 0
    load_stage(sbase, 0, m0, n0, 0, tid);
    asm volatile("cp.async.commit_group;\n" ::);

#pragma unroll 8
    for (int it = 0; it < KITERS; ++it) {
        asm volatile("cp.async.wait_group 0;\n" ::);
        __syncthreads();

        if (it + 1 < KITERS)
            load_stage(sbase, (it + 1) & 1, m0, n0, (it + 1) * BK, tid);
        asm volatile("cp.async.commit_group;\n" ::);

        const uint32_t sa = sbase + (it & 1) * STG_BYTES;
        const uint32_t sb = sa + A_BYTES;

#pragma unroll
        for (int kk = 0; kk < BK / 16; ++kk) {      // 8 k-chunks; sub-tile = kk>>2
            const uint32_t sah = sa + (kk >> 2) * A_SUB;
            const uint32_t sbh = sb + (kk >> 2) * B_SUB;
            const int kk2 = kk & 3;
            uint32_t af[4][4], bf[4][2];
#pragma unroll
            for (int mt = 0; mt < 4; ++mt) {
                int r = a_row[mt];
                ldsm_x4(af[mt], sah + r * 128 + (((kk2 * 2 + a_kt) ^ (r & 7)) << 4));
            }
#pragma unroll
            for (int nt = 0; nt < 4; ++nt) {
                int r = b_row[nt];
                ldsm_x2(bf[nt], sbh + r * 128 + (((kk2 * 2 + b_kt) ^ (r & 7)) << 4));
            }
#pragma unroll
            for (int mt = 0; mt < 4; ++mt)
#pragma unroll
                for (int nt = 0; nt < 4; ++nt)
                    mma_f16(acc[mt][nt], af[mt], bf[nt]);
        }
    }

    // Epilogue
#pragma unroll
    for (int mt = 0; mt < 4; ++mt) {
        int r0 = m0 + wm * 64 + mt * 16 + g;
#pragma unroll
        for (int nt = 0; nt < 4; ++nt) {
            int col = n0 + wn * 32 + nt * 8 + 2 * tg;
            *(float2*)(C + (size_t)r0 * OUT_F + col) =
                make_float2(acc[mt][nt][0], acc[mt][nt][1]);
            *(float2*)(C + (size_t)(r0 + 8) * OUT_F + col) =
                make_float2(acc[mt][nt][2], acc[mt][nt][3]);
        }
    }
}

// ---------------------------------------------------------------------------
extern "C" void kernel_launch(void* const* d_in, const int* in_sizes, int n_in,
                              void* d_out, int out_size) {
    const float* x    = (const float*)d_in[0];
    const float* grid = (const float*)d_in[1];
    const float* bw   = (const float*)d_in[2];
    const float* sw   = (const float*)d_in[3];
    const float* sc   = (const float*)d_in[4];
    float* out = (float*)d_out;

    prep_w<<<1024, 256>>>(bw, sw, sc);
    prep_act<<<(BATCH * IN_F) / 512, 256>>>(x, grid);

    cudaFuncSetAttribute(kan_gemm, cudaFuncAttributeMaxDynamicSharedMemorySize, GEMM_SMEM);
    dim3 grd(OUT_F / BN, BATCH / BM);   // 4 x 64 = 256 CTAs
    kan_gemm<<<grd, 512, GEMM_SMEM>>>(out);
}